// round 9
// baseline (speedup 1.0000x reference)
#include <cuda_runtime.h>
#include <math.h>

// HouseholderRoPE: B=2,H=16,T=8192,D=64,M=8
// out = concat(q_rot, k_rot), float32, 2*B*H*T*D elements.
//
// Kernel 1 (merged setup): cos/sin table (fp32 Cody-Waite mod-2pi, validated
//   earlier at rel ~1.9e-7) + per-head Y and W = Y*T (compact WY:
//   P0*..*P7 = I - Y T Y^T).
// Kernel 2 (main): each thread processes q+k of BOTH batches at one (h,t)
//   (shared Y/W/cs amortized over 4 rows), and each block runs a 4-deep
//   software pipeline over consecutive t-tiles: tile i+1's loads are issued
//   before tile i's compute, so DRAM never idles during the compute phase.

#define BB 2
#define HH 16
#define TT 8192
#define DD 64
#define MM 8
#define EPSF 1e-8f

#define TPB 256
#define T_PER_BLOCK 32   // 8 warps * 4 t-rows per warp (x2 batches per thread)
#define ITERS 4          // t-tiles per block, pipelined

__device__ float g_Y[HH * MM * DD];
__device__ float g_W[HH * MM * DD];
__device__ float g_cs[TT * DD];   // per t: 32 pairs * (cos,sin) interleaved

// ---- packed f32x2 helpers --------------------------------------------------
typedef unsigned long long ull;

__device__ __forceinline__ ull pk2(float lo, float hi) {
    ull r; asm("mov.b64 %0, {%1, %2};" : "=l"(r) : "f"(lo), "f"(hi)); return r;
}
__device__ __forceinline__ void upk2(ull v, float& lo, float& hi) {
    asm("mov.b64 {%0, %1}, %2;" : "=f"(lo), "=f"(hi) : "l"(v));
}
__device__ __forceinline__ ull fma2(ull a, ull b, ull c) {
    ull d; asm("fma.rn.f32x2 %0, %1, %2, %3;" : "=l"(d) : "l"(a), "l"(b), "l"(c));
    return d;
}
__device__ __forceinline__ ull mul2(ull a, ull b) {
    ull d; asm("mul.rn.f32x2 %0, %1, %2;" : "=l"(d) : "l"(a), "l"(b));
    return d;
}

// ---------------------------------------------------------------------------
// Merged setup kernel. 1040 blocks x 256 threads.
// ---------------------------------------------------------------------------
__global__ void setup_kernel(const float* __restrict__ V,
                             const float* __restrict__ pos,
                             const float* __restrict__ freq) {
    if (blockIdx.x < 1024) {
        // cos/sin table, fp32 Cody-Waite mod-2pi (k<=1304: k*6.28125 exact).
        int idx = blockIdx.x * 256 + threadIdx.x;   // 0..262143
        int t = idx >> 5;
        int p = idx & 31;
        float ang = pos[t] * freq[p];               // fp32 product, as reference
        float kq  = rintf(ang * 0.15915494309189535f);
        float r   = fmaf(kq, -6.28125f, ang);
        r = fmaf(kq, -1.9353072e-3f, r);
        g_cs[t * 64 + 2 * p]     = cosf(r);
        g_cs[t * 64 + 2 * p + 1] = sinf(r);
        return;
    }

    // ---- per-head Y, T, W ---------------------------------------------------
    const int hh  = blockIdx.x - 1024;            // 0..15
    const int tid = threadIdx.x;

    __shared__ float sY[MM * DD];
    __shared__ float sv2[MM * DD];
    __shared__ float sG[MM * MM];
    __shared__ float sT[MM * MM];
    __shared__ float rnorm[MM];

    float v0 = V[hh * (MM * DD) + tid];
    float v1 = V[hh * (MM * DD) + 256 + tid];
    sv2[tid]       = v0 * v0;
    sv2[tid + 256] = v1 * v1;
    __syncthreads();

    if (tid < MM) {
        float s = EPSF * EPSF;
        #pragma unroll 8
        for (int i = 0; i < DD; i++) s += sv2[tid * DD + i];
        rnorm[tid] = 1.0f / sqrtf(s);
    }
    __syncthreads();

    sY[tid]       = v0 * rnorm[tid >> 6];
    sY[tid + 256] = v1 * rnorm[(tid + 256) >> 6];
    if (tid < MM * MM) sT[tid] = (tid % 9 == 0) ? 2.0f : 0.0f;  // diag = 2
    __syncthreads();

    if (tid < 64) {                               // Gram G[i][j] = u_i . u_j
        int gi = tid >> 3, gj = tid & 7;
        float s = 0.0f;
        #pragma unroll 8
        for (int dd = 0; dd < DD; dd++) s += sY[gi * DD + dd] * sY[gj * DD + dd];
        sG[tid] = s;
    }
    __syncthreads();

    // T recurrence (lanes 0..7 of warp 0, parallel over row i):
    //   T[i][j] = -2 * sum_{k=i..j-1} T[i][k] * G[k][j],  i<j ; diag = 2.
    if (tid < 8) {
        const int i = tid;
        #pragma unroll
        for (int j2 = 1; j2 < MM; j2++) {
            float acc = 0.0f;
            if (i < j2) {
                for (int kk = i; kk < j2; kk++) acc += sT[i * 8 + kk] * sG[kk * 8 + j2];
            }
            __syncwarp(0x000000ffu);
            if (i < j2) sT[i * 8 + j2] = -2.0f * acc;
            __syncwarp(0x000000ffu);
        }
    }
    __syncthreads();

    // W[:,m] = sum_{k<=m} u_k * T[k][m]  (two elements per thread) + export Y
    {
        int e0 = tid, e1 = tid + 256;
        int m0 = e0 >> 6, m1 = e1 >> 6;
        int d0 = e0 & 63, d1 = e1 & 63;
        float w0 = 0.0f, w1 = 0.0f;
        for (int kk = 0; kk <= m0; kk++) w0 += sY[kk * DD + d0] * sT[kk * 8 + m0];
        for (int kk = 0; kk <= m1; kk++) w1 += sY[kk * DD + d1] * sT[kk * 8 + m1];
        g_W[hh * (MM * DD) + e0] = w0;
        g_W[hh * (MM * DD) + e1] = w1;
        g_Y[hh * (MM * DD) + e0] = sY[e0];
        g_Y[hh * (MM * DD) + e1] = sY[e1];
    }
}

// ---------------------------------------------------------------------------
// Main kernel: pipelined over ITERS t-tiles; 8 lanes per row, 4 t-rows per
// warp; each thread handles q and k of BOTH batches at its (h,t).
// ---------------------------------------------------------------------------
__global__ void __launch_bounds__(TPB, 2) hh_rope_kernel(
    const float* __restrict__ q, const float* __restrict__ k,
    float* __restrict__ out)
{
    __shared__ float sY[MM * DD];
    __shared__ float sW[MM * DD];

    const int h  = blockIdx.x >> 6;               // 0..15  (16 * 64 blocks)
    const int tg = blockIdx.x & 63;

    const int tid  = threadIdx.x;
    const int lane = tid & 31;
    const int warp = tid >> 5;
    const int j    = lane & 7;                    // d-slice within row
    const int g    = lane >> 3;                   // t row within warp

    const int t0 = tg * (T_PER_BLOCK * ITERS) + warp * 4 + g;
    const size_t bstr4 = (size_t)HH * TT * (DD / 4);            // batch stride
    const size_t koff  = (size_t)BB * bstr4;
    size_t row = ((size_t)h * TT + t0) * (DD / 4);              // b = 0, tile 0

    const float4* q4  = (const float4*)q;
    const float4* k4  = (const float4*)k;
    const float4* cs4 = (const float4*)g_cs;      // L2-resident
    float4* o4 = (float4*)out;

    // Stage Y/W; tile-0 loads issued first so they fly during staging.
    float4 q0a = __ldcs(&q4[row + j]);
    float4 q0b = __ldcs(&q4[row + 8 + j]);
    float4 k0a = __ldcs(&k4[row + j]);
    float4 k0b = __ldcs(&k4[row + 8 + j]);
    float4 q1a = __ldcs(&q4[row + bstr4 + j]);
    float4 q1b = __ldcs(&q4[row + bstr4 + 8 + j]);
    float4 k1a = __ldcs(&k4[row + bstr4 + j]);
    float4 k1b = __ldcs(&k4[row + bstr4 + 8 + j]);

    sY[tid]       = __ldg(&g_Y[h * (MM * DD) + tid]);
    sY[tid + 256] = __ldg(&g_Y[h * (MM * DD) + 256 + tid]);
    sW[tid]       = __ldg(&g_W[h * (MM * DD) + tid]);
    sW[tid + 256] = __ldg(&g_W[h * (MM * DD) + 256 + tid]);
    __syncthreads();

    #pragma unroll
    for (int it = 0; it < ITERS; it++) {
        // ---- Prefetch next tile (in flight during this tile's compute) -----
        const size_t rown = row + (size_t)T_PER_BLOCK * (DD / 4);
        float4 nq0a, nq0b, nk0a, nk0b, nq1a, nq1b, nk1a, nk1b;
        if (it + 1 < ITERS) {
            nq0a = __ldcs(&q4[rown + j]);
            nq0b = __ldcs(&q4[rown + 8 + j]);
            nk0a = __ldcs(&k4[rown + j]);
            nk0b = __ldcs(&k4[rown + 8 + j]);
            nq1a = __ldcs(&q4[rown + bstr4 + j]);
            nq1b = __ldcs(&q4[rown + bstr4 + 8 + j]);
            nk1a = __ldcs(&k4[rown + bstr4 + j]);
            nk1b = __ldcs(&k4[rown + bstr4 + 8 + j]);
        }
        const int t = t0 + it * T_PER_BLOCK;
        float4 ca = __ldg(&cs4[(size_t)t * 16 + j]);
        float4 cb = __ldg(&cs4[(size_t)t * 16 + 8 + j]);

        // ---- Pack into f32x2 pairs -----------------------------------------
        ull q0p0 = pk2(q0a.x, q0a.y), q0p1 = pk2(q0a.z, q0a.w);
        ull q0p2 = pk2(q0b.x, q0b.y), q0p3 = pk2(q0b.z, q0b.w);
        ull k0p0 = pk2(k0a.x, k0a.y), k0p1 = pk2(k0a.z, k0a.w);
        ull k0p2 = pk2(k0b.x, k0b.y), k0p3 = pk2(k0b.z, k0b.w);
        ull q1p0 = pk2(q1a.x, q1a.y), q1p1 = pk2(q1a.z, q1a.w);
        ull q1p2 = pk2(q1b.x, q1b.y), q1p3 = pk2(q1b.z, q1b.w);
        ull k1p0 = pk2(k1a.x, k1a.y), k1p1 = pk2(k1a.z, k1a.w);
        ull k1p2 = pk2(k1b.x, k1b.y), k1p3 = pk2(k1b.z, k1b.w);

        // ---- s = Y^T z for all four rows (one set of Y loads) --------------
        float s0q[MM], s0k[MM], s1q[MM], s1k[MM];
        #pragma unroll
        for (int mm = 0; mm < MM; mm++) {
            float4 ya = *(const float4*)&sY[mm * DD + 4 * j];
            float4 yb = *(const float4*)&sY[mm * DD + 32 + 4 * j];
            ull ya01 = pk2(ya.x, ya.y), ya23 = pk2(ya.z, ya.w);
            ull yb01 = pk2(yb.x, yb.y), yb23 = pk2(yb.z, yb.w);
            float lo, hi;
            ull a;
            a = fma2(q0p0, ya01, fma2(q0p1, ya23, fma2(q0p2, yb01, mul2(q0p3, yb23))));
            upk2(a, lo, hi); s0q[mm] = lo + hi;
            a = fma2(k0p0, ya01, fma2(k0p1, ya23, fma2(k0p2, yb01, mul2(k0p3, yb23))));
            upk2(a, lo, hi); s0k[mm] = lo + hi;
            a = fma2(q1p0, ya01, fma2(q1p1, ya23, fma2(q1p2, yb01, mul2(q1p3, yb23))));
            upk2(a, lo, hi); s1q[mm] = lo + hi;
            a = fma2(k1p0, ya01, fma2(k1p1, ya23, fma2(k1p2, yb01, mul2(k1p3, yb23))));
            upk2(a, lo, hi); s1k[mm] = lo + hi;
        }

        // ---- Butterfly all-reduce across the 8 lanes of each row group -----
        #pragma unroll
        for (int off = 1; off < 8; off <<= 1) {
            #pragma unroll
            for (int mm = 0; mm < MM; mm++) {
                s0q[mm] += __shfl_xor_sync(0xffffffffu, s0q[mm], off);
                s0k[mm] += __shfl_xor_sync(0xffffffffu, s0k[mm], off);
                s1q[mm] += __shfl_xor_sync(0xffffffffu, s1q[mm], off);
                s1k[mm] += __shfl_xor_sync(0xffffffffu, s1k[mm], off);
            }
        }

        // ---- z -= W s (one set of W loads serves all four rows) ------------
        #pragma unroll
        for (int mm = 0; mm < MM; mm++) {
            float4 wa = *(const float4*)&sW[mm * DD + 4 * j];
            float4 wb = *(const float4*)&sW[mm * DD + 32 + 4 * j];
            ull wa01 = pk2(wa.x, wa.y), wa23 = pk2(wa.z, wa.w);
            ull wb01 = pk2(wb.x, wb.y), wb23 = pk2(wb.z, wb.w);
            ull n;
            n = pk2(-s0q[mm], -s0q[mm]);
            q0p0 = fma2(wa01, n, q0p0); q0p1 = fma2(wa23, n, q0p1);
            q0p2 = fma2(wb01, n, q0p2); q0p3 = fma2(wb23, n, q0p3);
            n = pk2(-s0k[mm], -s0k[mm]);
            k0p0 = fma2(wa01, n, k0p0); k0p1 = fma2(wa23, n, k0p1);
            k0p2 = fma2(wb01, n, k0p2); k0p3 = fma2(wb23, n, k0p3);
            n = pk2(-s1q[mm], -s1q[mm]);
            q1p0 = fma2(wa01, n, q1p0); q1p1 = fma2(wa23, n, q1p1);
            q1p2 = fma2(wb01, n, q1p2); q1p3 = fma2(wb23, n, q1p3);
            n = pk2(-s1k[mm], -s1k[mm]);
            k1p0 = fma2(wa01, n, k1p0); k1p1 = fma2(wa23, n, k1p1);
            k1p2 = fma2(wb01, n, k1p2); k1p3 = fma2(wb23, n, k1p3);
        }

        // ---- RoPE (even' = e*c - o*s ; odd' = e*s + o*c) -------------------
        float e, o;
        float4 r;
        upk2(q0p0, e, o); r.x = e*ca.x - o*ca.y; r.y = e*ca.y + o*ca.x;
        upk2(q0p1, e, o); r.z = e*ca.z - o*ca.w; r.w = e*ca.w + o*ca.z;
        __stcs(&o4[row + j], r);
        upk2(q0p2, e, o); r.x = e*cb.x - o*cb.y; r.y = e*cb.y + o*cb.x;
        upk2(q0p3, e, o); r.z = e*cb.z - o*cb.w; r.w = e*cb.w + o*cb.z;
        __stcs(&o4[row + 8 + j], r);
        upk2(k0p0, e, o); r.x = e*ca.x - o*ca.y; r.y = e*ca.y + o*ca.x;
        upk2(k0p1, e, o); r.z = e*ca.z - o*ca.w; r.w = e*ca.w + o*ca.z;
        __stcs(&o4[koff + row + j], r);
        upk2(k0p2, e, o); r.x = e*cb.x - o*cb.y; r.y = e*cb.y + o*cb.x;
        upk2(k0p3, e, o); r.z = e*cb.z - o*cb.w; r.w = e*cb.w + o*cb.z;
        __stcs(&o4[koff + row + 8 + j], r);
        upk2(q1p0, e, o); r.x = e*ca.x - o*ca.y; r.y = e*ca.y + o*ca.x;
        upk2(q1p1, e, o); r.z = e*ca.z - o*ca.w; r.w = e*ca.w + o*ca.z;
        __stcs(&o4[row + bstr4 + j], r);
        upk2(q1p2, e, o); r.x = e*cb.x - o*cb.y; r.y = e*cb.y + o*cb.x;
        upk2(q1p3, e, o); r.z = e*cb.z - o*cb.w; r.w = e*cb.w + o*cb.z;
        __stcs(&o4[row + bstr4 + 8 + j], r);
        upk2(k1p0, e, o); r.x = e*ca.x - o*ca.y; r.y = e*ca.y + o*ca.x;
        upk2(k1p1, e, o); r.z = e*ca.z - o*ca.w; r.w = e*ca.w + o*ca.z;
        __stcs(&o4[koff + row + bstr4 + j], r);
        upk2(k1p2, e, o); r.x = e*cb.x - o*cb.y; r.y = e*cb.y + o*cb.x;
        upk2(k1p3, e, o); r.z = e*cb.z - o*cb.w; r.w = e*cb.w + o*cb.z;
        __stcs(&o4[koff + row + bstr4 + 8 + j], r);

        // ---- Rotate pipeline ------------------------------------------------
        if (it + 1 < ITERS) {
            q0a = nq0a; q0b = nq0b; k0a = nk0a; k0b = nk0b;
            q1a = nq1a; q1b = nq1b; k1a = nk1a; k1b = nk1b;
            row = rown;
        }
    }
}

// ---------------------------------------------------------------------------
extern "C" void kernel_launch(void* const* d_in, const int* in_sizes, int n_in,
                              void* d_out, int out_size) {
    const float* q    = (const float*)d_in[0];
    const float* k    = (const float*)d_in[1];
    const float* V    = (const float*)d_in[2];
    const float* pos  = (const float*)d_in[3];
    const float* freq = (const float*)d_in[4];
    float* out = (float*)d_out;

    setup_kernel<<<1024 + HH, 256>>>(V, pos, freq);
    hh_rope_kernel<<<HH * (TT / (T_PER_BLOCK * ITERS)), TPB>>>(q, k, out);
}